// round 9
// baseline (speedup 1.0000x reference)
#include <cuda_runtime.h>

// RelativePosition: out[b, k(i,j)] = a[b,j] - a[b,i], j > i, row-major strict
// upper triangle. Row i: base(i) = i*(n-1) - i*(i-1)/2, len = n-1-i,
// out[base+t] = a[i+1+t] - a[i].
//
// R8 == R7 (resubmit after infra failure): wide register-resident windows +
// edge-scalar offload.
//  * Window w = sources [W, W+256), W = 256*w. Lane l holds 16 floats:
//    e0,e1 = window-relative u in [4l, 4l+7], e2,e3 = u in [128+4l, 128+4l+7].
//  * Row i, window w: S = base + W - i - 1, F0 = ceil(S/4), hp = (-S)&3.
//    Output float4 f = F0+k (k in [0,64)) needs u in [hp+4k, hp+4k+3].
//    Lane l stores k = lid (f0) and k = lid+32 (f1): both source sets are
//    subsets of the lane's own regs for ANY hp. Contiguous, predicated
//    (f in [fb, fe)) streaming STG.128. Windows tile exactly (F0 step 64).
//  * Head/tail scalars of every row handled by ONE edge block per batch.
//  * All 32-bit indexing; a[i] via lane-preload + 1 SHFL per row.

#define TPB 256
#define WSH 8
#define WW  256
#define RPW 16                 // rows per warp
#define RPB (RPW * (TPB / 32)) // rows per block-chunk = 128

__global__ void __launch_bounds__(TPB)
relpos_kernel(const float* __restrict__ in, float* __restrict__ out,
              int n, int P, int NW, int BPB)
{
    int b = blockIdx.x / BPB;
    int r = blockIdx.x - b * BPB;

    const int tid = threadIdx.x, wid = tid >> 5, lid = tid & 31;
    const float* __restrict__ arow = in + b * n;
    float* __restrict__ outb = out + b * P;      // b*P < 2^31

    // ---------------- edge block: head/tail scalars for all rows ----------
    if (r == BPB - 1) {
        for (int i = tid; i <= n - 2; i += TPB) {
            int base = i * (n - 1) - ((i * (i - 1)) >> 1);
            int len  = n - 1 - i;
            float ai = __ldg(arow + i);
            int fb = (base + 3) >> 2;
            int fe = (base + len) >> 2;
            if (fb < fe) {
                for (int o = base; o < (fb << 2); ++o)
                    outb[o] = __ldg(arow + (o - base + i + 1)) - ai;
                for (int o = (fe << 2); o < base + len; ++o)
                    outb[o] = __ldg(arow + (o - base + i + 1)) - ai;
            } else {
                for (int o = base; o < base + len; ++o)
                    outb[o] = __ldg(arow + (o - base + i + 1)) - ai;
            }
        }
        return;
    }

    // ---------------- decode r -> (window w, row-chunk) -------------------
    int w = 0, chunk = 0;
    {
        int acc = 0;
        #pragma unroll
        for (int ww = 0; ww < 8; ++ww) {
            if (ww >= NW) break;
            int Imx = min(ww * WW + WW - 2, n - 2);
            int C = (Imx + 1 + RPB - 1) / RPB;
            if (r < acc + C) { w = ww; chunk = r - acc; break; }
            acc += C;
        }
    }

    const int W = w << WSH;
    const int Imax = min(W + WW - 2, n - 2);
    int i0 = chunk * RPB + wid * RPW;
    if (i0 > Imax) return;                       // warp-uniform
    int iend = min(i0 + RPW, Imax + 1);

    // ---- source regs: u[4l..4l+7] and u[128+4l..128+4l+7] ----------------
    int A = W + 4 * lid;
    float4 e0 = *(const float4*)(arow + A);
    float4 e1 = *(const float4*)(arow + A + 4);                 // max 899 < n
    float4 e2 = *(const float4*)(arow + min(A + 128, n - 4));   // clamp: garbage
    float4 e3 = *(const float4*)(arow + min(A + 132, n - 4));   //   only feeds p1=false

    // ---- preload a[i] for the warp's rows (lanes 0..RPW-1) ---------------
    float a_pre = __ldg(arow + min(i0 + lid, n - 2));

    int i    = i0;
    int base = i * (n - 1) - ((i * (i - 1)) >> 1);
    int S    = base + W - i - 1;
    int len  = n - 1 - i;

    for (; i < iend; ++i) {
        float ai = __shfl_sync(0xffffffffu, a_pre, i - i0);

        int F0 = (S + 3) >> 2;                   // ceil(S/4), S >= -1 ok
        int hp = (-S) & 3;
        int fb = (base + 3) >> 2;
        int fe = (base + len) >> 2;
        int f0 = F0 + lid;
        int f1 = f0 + 32;
        bool p0 = (f0 >= fb) & (f0 < fe);
        bool p1 = (f1 >= fb) & (f1 < fe);

        float4 o0, o1;
        switch (hp) {                            // warp-uniform branch
        case 0:
            o0 = make_float4(e0.x - ai, e0.y - ai, e0.z - ai, e0.w - ai);
            o1 = make_float4(e2.x - ai, e2.y - ai, e2.z - ai, e2.w - ai);
            break;
        case 1:
            o0 = make_float4(e0.y - ai, e0.z - ai, e0.w - ai, e1.x - ai);
            o1 = make_float4(e2.y - ai, e2.z - ai, e2.w - ai, e3.x - ai);
            break;
        case 2:
            o0 = make_float4(e0.z - ai, e0.w - ai, e1.x - ai, e1.y - ai);
            o1 = make_float4(e2.z - ai, e2.w - ai, e3.x - ai, e3.y - ai);
            break;
        default:
            o0 = make_float4(e0.w - ai, e1.x - ai, e1.y - ai, e1.z - ai);
            o1 = make_float4(e2.w - ai, e3.x - ai, e3.y - ai, e3.z - ai);
            break;
        }
        if (p0) __stcs((float4*)outb + f0, o0);
        if (p1) __stcs((float4*)outb + f1, o1);

        S += n - 2 - i;                          // S(i+1) = S(i) + len(i) - 1
        base += len;
        --len;
    }
}

extern "C" void kernel_launch(void* const* d_in, const int* in_sizes, int n_in,
                              void* d_out, int out_size)
{
    const float* in = (const float*)d_in[0];
    float* out = (float*)d_out;

    long long total_in = in_sizes[0];                        // B * n
    int n = (int)(2LL * (long long)out_size / total_in + 1); // 1024
    int B = (int)(total_in / n);                             // 128
    int P = n * (n - 1) / 2;                                 // 523776 < 2^31

    int NW = n >> WSH;                                       // 4 windows
    int BPB = 1;                                             // + edge block
    for (int w = 0; w < NW; ++w) {
        int Imx = (w * WW + WW - 2 < n - 2) ? (w * WW + WW - 2) : (n - 2);
        BPB += (Imx + 1 + RPB - 1) / RPB;                    // chunks of 128 rows
    }                                                        // BPB = 21 for n=1024

    relpos_kernel<<<B * BPB, TPB>>>(in, out, n, P, NW, BPB);
}

// round 11
// speedup vs baseline: 1.0695x; 1.0695x over previous
#include <cuda_runtime.h>

// RelativePosition: out[b, k(i,j)] = a[b,j] - a[b,i], j > i, row-major
// strict upper triangle. Row i = contiguous output segment:
//   base(i) = i*(n-1) - i*(i-1)/2, len = n-1-i, out[base+t] = a[i+1+t] - a[i]
//
// R9 = R5 (best: 43.5us) with ONE change: __stcs -> __stwt (write-through)
// to test whether L2 dirty-line drain is the chip-level ceiling.
// Structure: 4 shifted smem copies -> aligned LDS.128; warp-per-row, rows
// paired g <-> n-2-g; 32-bit incremental bases; natural occupancy;
// conflict-free vectorized smem fill.

#define TPB 256
#define PW  2                 // pairs per warp
#define PPB (PW * (TPB / 32)) // pairs per block = 16
#define NMAX 1024

__device__ __forceinline__ void process_row(
    const float (*__restrict__ sm)[NMAX], float* __restrict__ outb,
    int n, int i, int base, int lid)
{
    int len  = n - 1 - i;
    float ai = sm[0][i];
    int src0 = i + 1;

    int head = (-base) & 3;
    if (head > len) head = len;
    if (lid < head) outb[base + lid] = sm[0][src0 + lid] - ai;

    int rem  = len - head;
    int nvec = rem >> 2;
    int x    = src0 + head;
    int sh   = x & 3;
    const float4* __restrict__ sp = (const float4*)(&sm[sh][x - sh]); // 16B aligned
    float4* __restrict__ dp = (float4*)(outb + base + head);          // 16B aligned

    #pragma unroll 4
    for (int v = lid; v < nvec; v += 32) {
        float4 q = sp[v];
        float4 o = make_float4(q.x - ai, q.y - ai, q.z - ai, q.w - ai);
        __stwt(dp + v, o);               // write-through STG.128
    }

    int tm = rem & 3;
    if (lid < tm) {
        int t = head + (nvec << 2) + lid;
        outb[base + t] = sm[0][src0 + t] - ai;
    }
}

__global__ void __launch_bounds__(TPB)
relpos_kernel(const float* __restrict__ in, float* __restrict__ out,
              int n, int G, int chunks, int P)
{
    __shared__ float sm[4][NMAX];

    int b = blockIdx.x / chunks;
    int c = blockIdx.x - b * chunks;
    const int tid = threadIdx.x;
    const int wid = tid >> 5;
    const int lid = tid & 31;

    const float* __restrict__ arow = in + b * n;
    float* __restrict__ outb = out + b * P;        // b*P < 2^31

    // ---- fill 4 shifted copies: sm[s][k] = a[k+s] (k <= n-1-s valid) ----
    // Conflict-free: per thread 2 LDG.128 + 4 STS.128, consecutive lane addrs.
    {
        const float4* __restrict__ in4 = (const float4*)arow;
        int nv4 = n >> 2;
        for (int t = tid; t < nv4; t += TPB) {
            float4 q0 = in4[t];
            float4 q1 = in4[(t + 1 < nv4) ? (t + 1) : t];
            float e[8] = {q0.x, q0.y, q0.z, q0.w, q1.x, q1.y, q1.z, q1.w};
            #pragma unroll
            for (int s = 0; s < 4; ++s) {
                float4 w = make_float4(e[s], e[s + 1], e[s + 2], e[s + 3]);
                *(float4*)(&sm[s][t << 2]) = w;
            }
        }
    }
    __syncthreads();

    int gs = c * PPB + wid * PW;   // this warp's first pair index

    // ---- rows i1 = gs .. gs+PW-1 (ascending, incremental base) ----
    {
        int i = gs;
        int base = i * (n - 1) - ((i * (i - 1)) >> 1);
        #pragma unroll
        for (int p = 0; p < PW; ++p) {
            if (i < G) process_row(sm, outb, n, i, base, lid);
            base += n - 1 - i;
            ++i;
        }
    }
    // ---- rows i2 = n-2-gs, descending (incremental base) ----
    {
        int i2 = n - 2 - gs;
        int base2 = i2 * (n - 1) - ((i2 * (i2 - 1)) >> 1);
        #pragma unroll
        for (int p = 0; p < PW; ++p) {
            int g = gs + p;
            if (g < G && i2 > g) process_row(sm, outb, n, i2, base2, lid);
            base2 -= (n - i2);   // base(i2-1) = base(i2) - len(i2-1)
            --i2;
        }
    }
}

extern "C" void kernel_launch(void* const* d_in, const int* in_sizes, int n_in,
                              void* d_out, int out_size)
{
    const float* in = (const float*)d_in[0];
    float* out = (float*)d_out;

    long long total_in = in_sizes[0];                        // B * n
    int n = (int)(2LL * (long long)out_size / total_in + 1); // 1024
    int B = (int)(total_in / n);                             // 128
    int P = n * (n - 1) / 2;                                 // 523776 < 2^31

    int G = n / 2;                                           // pair groups (512)
    int chunks = (G + PPB - 1) / PPB;                        // 32

    relpos_kernel<<<B * chunks, TPB>>>(in, out, n, G, chunks, P);
}